// round 13
// baseline (speedup 1.0000x reference)
#include <cuda_runtime.h>
#include <math_constants.h>

#define N_NODES 8192
#define F_IN    256
#define F_OUT   64
#define ALPHA   0.2f
#define NEG_BIG -9e15f
#define SAFE_M  1e10f   // ULP(m) >> 88 -> all non-equal entries underflow to exactly 0
#define C_CAND  64
#define N_RUNS  32      // sortsel blocks
#define RUN_N   256     // keys per sortsel block
#define KEEP    64      // survivors per run

// Scratch (__device__ globals: allocation-free rule)
__device__ float          g_h[N_NODES * F_OUT];   // 2 MB
__device__ float          g_ssrc[N_NODES];
__device__ float          g_sdst[N_NODES];
__device__ float          g_run_key[N_RUNS * KEEP];   // 32 composite-sorted runs of 64
__device__ unsigned short g_run_idx[N_RUNS * KEEP];
__device__ float          g_cand_key[C_CAND];         // global bottom-64 of sdst, ascending
__device__ unsigned short g_cand_idx[C_CAND];
__device__ int            g_flag_list[N_NODES];
__device__ int            g_nflag;

// ---------------------------------------------------------------------------
// Kernel A: h = nodes @ W (8192x256 @ 256x64), fused s_src/s_dst epilogue.
// 16-row tiles -> 512 blocks. Resets g_nflag (graph-replay safe).
// ---------------------------------------------------------------------------
__global__ __launch_bounds__(256) void gemm_h_kernel(
    const float* __restrict__ nodes, const float* __restrict__ W,
    const float* __restrict__ a)
{
    __shared__ float As[16][68];
    __shared__ float Bs[64][68];

    const int tid = threadIdx.x;
    const int rowBase = blockIdx.x * 16;
    const int tr = tid >> 4;       // 1 row each
    const int tc = tid & 15;       // 4 cols each

    if (blockIdx.x == 0 && tid == 0) g_nflag = 0;

    float acc[4] = {};

    for (int k0 = 0; k0 < F_IN; k0 += 64) {
        {
            int r  = tid >> 4;
            int kq = (tid & 15) * 4;
            *(float4*)(&As[r][kq]) =
                *(const float4*)(nodes + (size_t)(rowBase + r) * F_IN + k0 + kq);
        }
#pragma unroll
        for (int it = 0; it < 4; it++) {
            int idx = tid + it * 256;
            int k   = idx >> 4;
            int nq  = (idx & 15) * 4;
            *(float4*)(&Bs[k][nq]) = *(const float4*)(W + (size_t)(k0 + k) * F_OUT + nq);
        }
        __syncthreads();

#pragma unroll
        for (int kk = 0; kk < 64; kk++) {
            float a0 = As[tr][kk];
            float4 b4 = *(const float4*)(&Bs[kk][tc * 4]);
            acc[0] += a0 * b4.x; acc[1] += a0 * b4.y;
            acc[2] += a0 * b4.z; acc[3] += a0 * b4.w;
        }
        __syncthreads();
    }

    *(float4*)(g_h + (size_t)(rowBase + tr) * F_OUT + tc * 4) =
        make_float4(acc[0], acc[1], acc[2], acc[3]);

    // Fused score epilogue: ssrc = h . a[:64], sdst = h . a[64:]
    float4 Asv = *(const float4*)(a + tc * 4);
    float4 Adv = *(const float4*)(a + F_OUT + tc * 4);
    float ps = acc[0] * Asv.x + acc[1] * Asv.y + acc[2] * Asv.z + acc[3] * Asv.w;
    float pd = acc[0] * Adv.x + acc[1] * Adv.y + acc[2] * Adv.z + acc[3] * Adv.w;
#pragma unroll
    for (int o = 1; o < 16; o <<= 1) {
        ps += __shfl_xor_sync(0xffffffffu, ps, o);
        pd += __shfl_xor_sync(0xffffffffu, pd, o);
    }
    if (tc == 0) {
        g_ssrc[rowBase + tr] = ps;
        g_sdst[rowBase + tr] = pd;
    }
}

// ---------------------------------------------------------------------------
// Kernel B1 (sortsel): 32 parallel blocks; block b composite-sorts its 256
// sdst keys (key asc, idx tiebreak) and emits the bottom 64.
// Any global-bottom-64 element has chunk-rank < 64, so it survives.
// ---------------------------------------------------------------------------
__global__ __launch_bounds__(RUN_N) void sortsel_kernel()
{
    __shared__ float          skey[RUN_N];
    __shared__ unsigned short sidx[RUN_N];

    const int tid  = threadIdx.x;
    const int base = blockIdx.x * RUN_N;
    skey[tid] = g_sdst[base + tid];
    sidx[tid] = (unsigned short)(base + tid);
    __syncthreads();

    for (int k = 2; k <= RUN_N; k <<= 1) {
        for (int j = k >> 1; j > 0; j >>= 1) {
            int ixj = tid ^ j;
            if (ixj > tid) {
                bool up = ((tid & k) == 0);
                float a = skey[tid], b = skey[ixj];
                unsigned short ai = sidx[tid], bi = sidx[ixj];
                bool a_gt_b = (a > b) || (a == b && ai > bi);   // composite, strict
                if (up ? a_gt_b : !a_gt_b) {
                    skey[tid] = b; skey[ixj] = a;
                    sidx[tid] = bi; sidx[ixj] = ai;
                }
            }
            __syncthreads();
        }
    }
    if (tid < KEEP) {
        g_run_key[blockIdx.x * KEEP + tid] = skey[tid];
        g_run_idx[blockIdx.x * KEEP + tid] = sidx[tid];
    }
}

// ---------------------------------------------------------------------------
// Kernel B2 (rankmerge): 2048 survivors; each computes its exact global rank
// = pos-in-own-run + sum over the other 31 runs of composite lower_bound.
// rank < 64 -> write g_cand[rank]. No sort. (lower_bound as a full while
// loop: interval 64 needs up to 7 halvings — a fixed 6-step unroll was the
// R12 bug: last size-1 interval never examined -> ranks off by up to 31.)
// ---------------------------------------------------------------------------
__global__ __launch_bounds__(1024) void rankmerge_kernel()
{
    __shared__ float          skey[N_RUNS * KEEP];   // 8 KB
    __shared__ unsigned short sidx[N_RUNS * KEEP];   // 4 KB

    const int tid = threadIdx.x;
    for (int t = tid; t < N_RUNS * KEEP; t += 1024) {
        skey[t] = g_run_key[t];
        sidx[t] = g_run_idx[t];
    }
    __syncthreads();

    const int e = blockIdx.x * 1024 + tid;           // 0..2047
    const int r = e >> 6;                            // own run
    const int p = e & 63;                            // pos in own run
    const float          key = skey[e];
    const unsigned short idx = sidx[e];

    int rank = p;
    for (int r2 = 0; r2 < N_RUNS; r2++) {
        if (r2 == r) continue;
        int lo = 0, hi = KEEP;
        while (lo < hi) {                            // exact lower_bound
            int mid = (lo + hi) >> 1;
            float          k2 = skey[r2 * KEEP + mid];
            unsigned short i2 = sidx[r2 * KEEP + mid];
            bool lt = (k2 < key) || (k2 == key && i2 < idx);
            if (lt) lo = mid + 1; else hi = mid;
        }
        rank += lo;
    }
    if (rank < C_CAND) {
        g_cand_key[rank] = key;
        g_cand_idx[rank] = idx;
    }
}

// ---------------------------------------------------------------------------
// Kernel C (pick): warp per row. For masked j (adj<=0.5),
// v = leaky(ssrc+sdst_j)*NEG_BIG is monotone non-increasing along ascending
// sdst, so the row max over masked j is the FIRST masked candidate, and its
// float-equal tie run is contiguous. Probe adj only at the 64 candidates.
// Flag for exact dense fallback if: no masked candidate, tie run reaches the
// window end, or winner |v| < SAFE_M.
// ---------------------------------------------------------------------------
__global__ __launch_bounds__(256) void pick_kernel(
    const float* __restrict__ adj, float* __restrict__ out)
{
    __shared__ float          ck[C_CAND];
    __shared__ unsigned short ci[C_CAND];
    if (threadIdx.x < C_CAND) {
        ck[threadIdx.x] = g_cand_key[threadIdx.x];
        ci[threadIdx.x] = g_cand_idx[threadIdx.x];
    }
    __syncthreads();

    const int warp = threadIdx.x >> 5;
    const int lane = threadIdx.x & 31;
    const int row  = blockIdx.x * 8 + warp;

    const float ssrc = g_ssrc[row];
    const float* adjrow = adj + (size_t)row * N_NODES;

    float m = 0.0f;
    bool found = false, open_end = false;
    float hacc0 = 0.0f, hacc1 = 0.0f, cnt = 0.0f;
    int base = 0;

    while (base < C_CAND) {
        const int k = base + lane;
        float key = ck[k];
        int   idx = (int)ci[k];
        // EXACT same fp32 expression as the dense path:
        float s  = ssrc + key;
        float e  = fmaxf(s, ALPHA * s);
        float vm = e * NEG_BIG;
        float av = __ldg(adjrow + idx);
        bool masked = !(av > 0.5f);

        unsigned mball = __ballot_sync(0xffffffffu, masked);
        if (!found) {
            if (mball == 0) { base += 32; continue; }
            int b0 = __ffs(mball) - 1;
            m = __shfl_sync(0xffffffffu, vm, b0);
            found = true;
        }
        unsigned tie = __ballot_sync(0xffffffffu, masked && (vm == m));
        while (tie) {
            int b = __ffs(tie) - 1;
            tie &= tie - 1;
            int j = __shfl_sync(0xffffffffu, idx, b);
            float2 hv = *(const float2*)(g_h + (size_t)j * F_OUT + lane * 2);
            hacc0 += hv.x;
            hacc1 += hv.y;
            cnt   += 1.0f;
        }
        float vend = __shfl_sync(0xffffffffu, vm, 31);   // smallest vm in window
        base += 32;
        if (vend != m) { open_end = false; break; }      // tie run closed
        open_end = true;                                 // may extend past window
    }

    bool flagged = (!found) || open_end;

    if (!flagged && m >= SAFE_M) {
        float inv = 1.0f / cnt;
        float o0 = hacc0 * inv;
        float o1 = hacc1 * inv;
        o0 = fmaxf(o0, ALPHA * o0);
        o1 = fmaxf(o1, ALPHA * o1);
        *(float2*)(out + (size_t)row * F_OUT + lane * 2) = make_float2(o0, o1);
    } else if (lane == 0) {
        int p = atomicAdd(&g_nflag, 1);
        g_flag_list[p] = row;
    }
}

// ---------------------------------------------------------------------------
// Kernel D (pass2): exact dense softmax for flagged rows (~0-3), one block
// per row, fused max + softmax-GEMV + normalize (block-local barrier).
// ---------------------------------------------------------------------------
__global__ __launch_bounds__(1024) void pass2_kernel(
    const float* __restrict__ adj, float* __restrict__ out)
{
    __shared__ float red[32];
    __shared__ float m_s;
    __shared__ float sacc[16][65];     // [jl][d], +l in [.][64]

    const int nflag = g_nflag;
    if (nflag == 0) return;

    const int tid  = threadIdx.x;
    const int warp = tid >> 5;
    const int lane = tid & 31;
    const int d    = tid & 63;
    const int jl   = tid >> 6;         // 0..15

    for (int f = blockIdx.x; f < nflag; f += gridDim.x) {
        const int row = g_flag_list[f];
        const float ssrc = g_ssrc[row];
        const float* adjrow = adj + (size_t)row * N_NODES;

        // Phase 1: true row max
        float mx = -CUDART_INF_F;
#pragma unroll
        for (int t = 0; t < 8; t++) {
            int j = tid + t * 1024;
            float av = __ldg(adjrow + j);
            float s  = ssrc + g_sdst[j];
            float e  = fmaxf(s, ALPHA * s);
            float v  = (av > 0.5f) ? e : e * NEG_BIG;
            mx = fmaxf(mx, v);
        }
#pragma unroll
        for (int o = 16; o; o >>= 1)
            mx = fmaxf(mx, __shfl_xor_sync(0xffffffffu, mx, o));
        if (lane == 0) red[warp] = mx;
        __syncthreads();
        if (tid < 32) {
            float r = red[lane];
#pragma unroll
            for (int o = 16; o; o >>= 1)
                r = fmaxf(r, __shfl_xor_sync(0xffffffffu, r, o));
            if (lane == 0) m_s = r;
        }
        __syncthreads();
        const float m = m_s;

        // Phase 2: softmax-weighted GEMV. jl-group owns j in [jl*512, jl*512+512);
        // within a warp adj/sdst loads are uniform (broadcast), h loads coalesced.
        float acc = 0.0f, lsum = 0.0f;
        const int j0 = jl * 512;
        for (int t = 0; t < 512; t++) {
            int j = j0 + t;
            float av = __ldg(adjrow + j);
            float s  = ssrc + g_sdst[j];
            float e  = fmaxf(s, ALPHA * s);
            float v  = (av > 0.5f) ? e : e * NEG_BIG;
            float p  = __expf(v - m);
            acc += p * g_h[(size_t)j * F_OUT + d];
            if (d == 0) lsum += p;
        }
        sacc[jl][d] = acc;
        if (d == 0) sacc[jl][64] = lsum;
        __syncthreads();

        if (tid < 64) {
            float o = 0.0f, l = 0.0f;
#pragma unroll
            for (int g = 0; g < 16; g++) { o += sacc[g][tid]; l += sacc[g][64]; }
            o /= l;
            o = fmaxf(o, ALPHA * o);
            out[(size_t)row * F_OUT + tid] = o;
        }
        __syncthreads();
    }
}

// ---------------------------------------------------------------------------
extern "C" void kernel_launch(void* const* d_in, const int* in_sizes, int n_in,
                              void* d_out, int out_size)
{
    const float* nodes = (const float*)d_in[0];   // [8192, 256]
    const float* adj   = (const float*)d_in[1];   // [8192, 8192]
    const float* W     = (const float*)d_in[2];   // [256, 64]
    const float* a     = (const float*)d_in[3];   // [128]
    float* out = (float*)d_out;                   // [8192, 64]

    gemm_h_kernel<<<N_NODES / 16, 256>>>(nodes, W, a);
    sortsel_kernel<<<N_RUNS, RUN_N>>>();
    rankmerge_kernel<<<2, 1024>>>();
    pick_kernel<<<N_NODES / 8, 256>>>(adj, out);
    pass2_kernel<<<8, 1024>>>(adj, out);
}

// round 14
// speedup vs baseline: 13.7083x; 13.7083x over previous
#include <cuda_runtime.h>
#include <math_constants.h>

#define N_NODES 8192
#define F_IN    256
#define F_OUT   64
#define ALPHA   0.2f
#define NEG_BIG -9e15f
#define SAFE_M  1e10f   // ULP(m) >> 88 -> all non-equal entries underflow to exactly 0
#define C_CAND  64
#define N_RUNS  32      // sortsel blocks
#define RUN_N   256     // keys per sortsel block
#define KEEP    64      // survivors per run

// Scratch (__device__ globals: allocation-free rule)
__device__ float          g_h[N_NODES * F_OUT];   // 2 MB
__device__ float          g_ssrc[N_NODES];
__device__ float          g_sdst[N_NODES];
__device__ float          g_run_key[N_RUNS * KEEP];   // 32 composite-sorted runs of 64
__device__ unsigned short g_run_idx[N_RUNS * KEEP];
__device__ float          g_cand_key[C_CAND];         // global bottom-64 of sdst, ascending
__device__ unsigned short g_cand_idx[C_CAND];
__device__ int            g_flag_list[N_NODES];
__device__ int            g_nflag;

// ---------------------------------------------------------------------------
// Kernel A: h = nodes @ W (8192x256 @ 256x64), fused s_src/s_dst epilogue.
// 16-row tiles -> 512 blocks. Resets g_nflag (graph-replay safe).
// ---------------------------------------------------------------------------
__global__ __launch_bounds__(256) void gemm_h_kernel(
    const float* __restrict__ nodes, const float* __restrict__ W,
    const float* __restrict__ a)
{
    __shared__ float As[16][68];
    __shared__ float Bs[64][68];

    const int tid = threadIdx.x;
    const int rowBase = blockIdx.x * 16;
    const int tr = tid >> 4;       // 1 row each
    const int tc = tid & 15;       // 4 cols each

    if (blockIdx.x == 0 && tid == 0) g_nflag = 0;

    float acc[4] = {};

    for (int k0 = 0; k0 < F_IN; k0 += 64) {
        {
            int r  = tid >> 4;
            int kq = (tid & 15) * 4;
            *(float4*)(&As[r][kq]) =
                *(const float4*)(nodes + (size_t)(rowBase + r) * F_IN + k0 + kq);
        }
#pragma unroll
        for (int it = 0; it < 4; it++) {
            int idx = tid + it * 256;
            int k   = idx >> 4;
            int nq  = (idx & 15) * 4;
            *(float4*)(&Bs[k][nq]) = *(const float4*)(W + (size_t)(k0 + k) * F_OUT + nq);
        }
        __syncthreads();

#pragma unroll
        for (int kk = 0; kk < 64; kk++) {
            float a0 = As[tr][kk];
            float4 b4 = *(const float4*)(&Bs[kk][tc * 4]);
            acc[0] += a0 * b4.x; acc[1] += a0 * b4.y;
            acc[2] += a0 * b4.z; acc[3] += a0 * b4.w;
        }
        __syncthreads();
    }

    *(float4*)(g_h + (size_t)(rowBase + tr) * F_OUT + tc * 4) =
        make_float4(acc[0], acc[1], acc[2], acc[3]);

    // Fused score epilogue: ssrc = h . a[:64], sdst = h . a[64:]
    float4 Asv = *(const float4*)(a + tc * 4);
    float4 Adv = *(const float4*)(a + F_OUT + tc * 4);
    float ps = acc[0] * Asv.x + acc[1] * Asv.y + acc[2] * Asv.z + acc[3] * Asv.w;
    float pd = acc[0] * Adv.x + acc[1] * Adv.y + acc[2] * Adv.z + acc[3] * Adv.w;
#pragma unroll
    for (int o = 1; o < 16; o <<= 1) {
        ps += __shfl_xor_sync(0xffffffffu, ps, o);
        pd += __shfl_xor_sync(0xffffffffu, pd, o);
    }
    if (tc == 0) {
        g_ssrc[rowBase + tr] = ps;
        g_sdst[rowBase + tr] = pd;
    }
}

// ---------------------------------------------------------------------------
// Kernel B1 (sortsel): 32 parallel blocks; block b composite-sorts its 256
// sdst keys (key asc, idx tiebreak) and emits the bottom 64.
// Any global-bottom-64 element has chunk-rank < 64, so it survives.
// ---------------------------------------------------------------------------
__global__ __launch_bounds__(RUN_N) void sortsel_kernel()
{
    __shared__ float          skey[RUN_N];
    __shared__ unsigned short sidx[RUN_N];

    const int tid  = threadIdx.x;
    const int base = blockIdx.x * RUN_N;
    skey[tid] = g_sdst[base + tid];
    sidx[tid] = (unsigned short)(base + tid);
    __syncthreads();

    for (int k = 2; k <= RUN_N; k <<= 1) {
        for (int j = k >> 1; j > 0; j >>= 1) {
            int ixj = tid ^ j;
            if (ixj > tid) {
                bool up = ((tid & k) == 0);
                float a = skey[tid], b = skey[ixj];
                unsigned short ai = sidx[tid], bi = sidx[ixj];
                bool a_gt_b = (a > b) || (a == b && ai > bi);   // composite, strict
                if (up ? a_gt_b : !a_gt_b) {
                    skey[tid] = b; skey[ixj] = a;
                    sidx[tid] = bi; sidx[ixj] = ai;
                }
            }
            __syncthreads();
        }
    }
    if (tid < KEEP) {
        g_run_key[blockIdx.x * KEEP + tid] = skey[tid];
        g_run_idx[blockIdx.x * KEEP + tid] = sidx[tid];
    }
}

// ---------------------------------------------------------------------------
// Kernel B2 (rankmerge): 2048 survivors; each computes its exact global rank
// = pos-in-own-run + sum over the other 31 runs of composite lower_bound
// (full while loop — 7 halvings for interval 64). rank < 64 -> g_cand[rank].
// ---------------------------------------------------------------------------
__global__ __launch_bounds__(1024) void rankmerge_kernel()
{
    __shared__ float          skey[N_RUNS * KEEP];   // 8 KB
    __shared__ unsigned short sidx[N_RUNS * KEEP];   // 4 KB

    const int tid = threadIdx.x;
    for (int t = tid; t < N_RUNS * KEEP; t += 1024) {
        skey[t] = g_run_key[t];
        sidx[t] = g_run_idx[t];
    }
    __syncthreads();

    const int e = blockIdx.x * 1024 + tid;           // 0..2047
    const int r = e >> 6;                            // own run
    const int p = e & 63;                            // pos in own run
    const float          key = skey[e];
    const unsigned short idx = sidx[e];

    int rank = p;
    for (int r2 = 0; r2 < N_RUNS; r2++) {
        if (r2 == r) continue;
        int lo = 0, hi = KEEP;
        while (lo < hi) {                            // exact lower_bound
            int mid = (lo + hi) >> 1;
            float          k2 = skey[r2 * KEEP + mid];
            unsigned short i2 = sidx[r2 * KEEP + mid];
            bool lt = (k2 < key) || (k2 == key && i2 < idx);
            if (lt) lo = mid + 1; else hi = mid;
        }
        rank += lo;
    }
    if (rank < C_CAND) {
        g_cand_key[rank] = key;
        g_cand_idx[rank] = idx;
    }
}

// ---------------------------------------------------------------------------
// Kernel C (pick): warp per row. For masked j (adj<=0.5),
// v = leaky(ssrc+sdst_j)*NEG_BIG is monotone non-increasing along ascending
// sdst, so the row max over masked j is the FIRST masked candidate, and its
// float-equal tie run is contiguous. Probe adj only at the 64 candidates.
// Flag for exact dense fallback if: no masked candidate, tie run reaches the
// window end, or winner |v| < SAFE_M.
// ---------------------------------------------------------------------------
__global__ __launch_bounds__(256) void pick_kernel(
    const float* __restrict__ adj, float* __restrict__ out)
{
    __shared__ float          ck[C_CAND];
    __shared__ unsigned short ci[C_CAND];
    if (threadIdx.x < C_CAND) {
        ck[threadIdx.x] = g_cand_key[threadIdx.x];
        ci[threadIdx.x] = g_cand_idx[threadIdx.x];
    }
    __syncthreads();

    const int warp = threadIdx.x >> 5;
    const int lane = threadIdx.x & 31;
    const int row  = blockIdx.x * 8 + warp;

    const float ssrc = g_ssrc[row];
    const float* adjrow = adj + (size_t)row * N_NODES;

    float m = 0.0f;
    bool found = false, open_end = false;
    float hacc0 = 0.0f, hacc1 = 0.0f, cnt = 0.0f;
    int base = 0;

    while (base < C_CAND) {
        const int k = base + lane;
        float key = ck[k];
        int   idx = (int)ci[k];
        // EXACT same fp32 expression as the dense path:
        float s  = ssrc + key;
        float e  = fmaxf(s, ALPHA * s);
        float vm = e * NEG_BIG;
        float av = __ldg(adjrow + idx);
        bool masked = !(av > 0.5f);

        unsigned mball = __ballot_sync(0xffffffffu, masked);
        if (!found) {
            if (mball == 0) { base += 32; continue; }
            int b0 = __ffs(mball) - 1;
            m = __shfl_sync(0xffffffffu, vm, b0);
            found = true;
        }
        unsigned tie = __ballot_sync(0xffffffffu, masked && (vm == m));
        while (tie) {
            int b = __ffs(tie) - 1;
            tie &= tie - 1;
            int j = __shfl_sync(0xffffffffu, idx, b);
            float2 hv = *(const float2*)(g_h + (size_t)j * F_OUT + lane * 2);
            hacc0 += hv.x;
            hacc1 += hv.y;
            cnt   += 1.0f;
        }
        float vend = __shfl_sync(0xffffffffu, vm, 31);   // smallest vm in window
        base += 32;
        if (vend != m) { open_end = false; break; }      // tie run closed
        open_end = true;                                 // may extend past window
    }

    bool flagged = (!found) || open_end;

    if (!flagged && m >= SAFE_M) {
        float inv = 1.0f / cnt;
        float o0 = hacc0 * inv;
        float o1 = hacc1 * inv;
        o0 = fmaxf(o0, ALPHA * o0);
        o1 = fmaxf(o1, ALPHA * o1);
        *(float2*)(out + (size_t)row * F_OUT + lane * 2) = make_float2(o0, o1);
    } else if (lane == 0) {
        int p = atomicAdd(&g_nflag, 1);
        g_flag_list[p] = row;
    }
}

// ---------------------------------------------------------------------------
// Kernel D (pass2): exact dense softmax for flagged rows, one block per row.
// CRITICAL (R13 lesson): compute exp ONCE per j into smem (8192 MUFU ops/row,
// 8/thread), never per (j,d) — the per-(j,d) version was 524K MUFU ops on one
// SM = ~580us/row. GEMV then reads p from smem (broadcast) with 4-way batched
// loads for MLP.
// ---------------------------------------------------------------------------
__global__ __launch_bounds__(1024) void pass2_kernel(
    const float* __restrict__ adj, float* __restrict__ out)
{
    __shared__ float p_s[N_NODES];     // 32 KB
    __shared__ float red[32];
    __shared__ float m_s;
    __shared__ float sacc[16][65];     // [jl][d] partials, +l in [.][64]

    const int nflag = g_nflag;
    if (nflag == 0) return;

    const int tid  = threadIdx.x;
    const int warp = tid >> 5;
    const int lane = tid & 31;
    const int d    = tid & 63;
    const int jl   = tid >> 6;         // 0..15

    for (int f = blockIdx.x; f < nflag; f += gridDim.x) {
        const int row = g_flag_list[f];
        const float ssrc = g_ssrc[row];
        const float* adjrow = adj + (size_t)row * N_NODES;

        // Phase 1: true row max (coalesced, 8 loads/thread)
        float mx = -CUDART_INF_F;
#pragma unroll
        for (int t = 0; t < 8; t++) {
            int j = tid + t * 1024;
            float av = __ldg(adjrow + j);
            float s  = ssrc + g_sdst[j];
            float e  = fmaxf(s, ALPHA * s);
            float v  = (av > 0.5f) ? e : e * NEG_BIG;
            mx = fmaxf(mx, v);
        }
#pragma unroll
        for (int o = 16; o; o >>= 1)
            mx = fmaxf(mx, __shfl_xor_sync(0xffffffffu, mx, o));
        if (lane == 0) red[warp] = mx;
        __syncthreads();
        if (tid < 32) {
            float r = red[lane];
#pragma unroll
            for (int o = 16; o; o >>= 1)
                r = fmaxf(r, __shfl_xor_sync(0xffffffffu, r, o));
            if (lane == 0) m_s = r;
        }
        __syncthreads();
        const float m = m_s;

        // Phase 2a: p_s[j] = exp(v_j - m), ONCE per j (coalesced)
#pragma unroll
        for (int t = 0; t < 8; t++) {
            int j = tid + t * 1024;
            float av = __ldg(adjrow + j);
            float s  = ssrc + g_sdst[j];
            float e  = fmaxf(s, ALPHA * s);
            float v  = (av > 0.5f) ? e : e * NEG_BIG;
            p_s[j] = __expf(v - m);
        }
        __syncthreads();

        // Phase 2b: GEMV. jl-group (2 warps) owns j in [jl*512, (jl+1)*512);
        // p from smem broadcast, h rows coalesced from L2. 4-way batched.
        float acc = 0.0f, lsum = 0.0f;
        const int j0 = jl * 512;
        for (int t = 0; t < 512; t += 4) {
            float p0 = p_s[j0 + t + 0];
            float p1 = p_s[j0 + t + 1];
            float p2 = p_s[j0 + t + 2];
            float p3 = p_s[j0 + t + 3];
            float h0 = g_h[(size_t)(j0 + t + 0) * F_OUT + d];
            float h1 = g_h[(size_t)(j0 + t + 1) * F_OUT + d];
            float h2 = g_h[(size_t)(j0 + t + 2) * F_OUT + d];
            float h3 = g_h[(size_t)(j0 + t + 3) * F_OUT + d];
            acc += p0 * h0 + p1 * h1 + p2 * h2 + p3 * h3;
            if (d == 0) lsum += (p0 + p1) + (p2 + p3);
        }
        sacc[jl][d] = acc;
        if (d == 0) sacc[jl][64] = lsum;
        __syncthreads();

        if (tid < 64) {
            float o = 0.0f, l = 0.0f;
#pragma unroll
            for (int g = 0; g < 16; g++) { o += sacc[g][tid]; l += sacc[g][64]; }
            o /= l;
            o = fmaxf(o, ALPHA * o);
            out[(size_t)row * F_OUT + tid] = o;
        }
        __syncthreads();
    }
}

// ---------------------------------------------------------------------------
extern "C" void kernel_launch(void* const* d_in, const int* in_sizes, int n_in,
                              void* d_out, int out_size)
{
    const float* nodes = (const float*)d_in[0];   // [8192, 256]
    const float* adj   = (const float*)d_in[1];   // [8192, 8192]
    const float* W     = (const float*)d_in[2];   // [256, 64]
    const float* a     = (const float*)d_in[3];   // [128]
    float* out = (float*)d_out;                   // [8192, 64]

    gemm_h_kernel<<<N_NODES / 16, 256>>>(nodes, W, a);
    sortsel_kernel<<<N_RUNS, RUN_N>>>();
    rankmerge_kernel<<<2, 1024>>>();
    pick_kernel<<<N_NODES / 8, 256>>>(adj, out);
    pass2_kernel<<<256, 1024>>>(adj, out);
}